// round 3
// baseline (speedup 1.0000x reference)
#include <cuda_runtime.h>

// GLoCELayerOutProp: B=4, T=1024, D=2048, N=8 concepts, S=8, H=8, ETA=1.
//
// Reformulation:
//   y[n,s]   = x·W[n,:,s] - muW[n,s],          muW precomputed per block
//   ||x-mu||^2 = ||x||^2 - 2 x·mu + ||mu||^2
//   score[n] = sum_s y^2 / ||x-mu||^2
//   gate, argmax, top-1 LoRA blend as before.
//
// Block = 512 threads (16 warps), TB=8 tokens, 64KB x tile in smem.
//   phase 0b: warps 0-7 -> per-token ||x||^2; warps 8-15 -> muW / ||mu||^2.
//   phase 1 : warp w -> concept w>>1, token group (w&1)*4..+3 (4 tokens,
//             40 accumulator regs -> fits 2 blocks/SM at <=64 regs).
//   phase 2 : warp w -> token w>>1, D-half w&1; h[8] combined via smem.

#define DD      2048
#define NCON    8
#define SR      8
#define HR      8
#define TB      8
#define NT      512

__device__ __forceinline__ float warp_sum(float v) {
    #pragma unroll
    for (int o = 16; o > 0; o >>= 1) v += __shfl_xor_sync(0xffffffffu, v, o);
    return v;
}

__global__ void __launch_bounds__(NT, 2)
gloce_kernel(const float* __restrict__ x,
             const float* __restrict__ Wsel,      // [N,D,S]
             const float* __restrict__ mu,        // [N,D]
             const float* __restrict__ center,    // [N]
             const float* __restrict__ slope,     // [N]
             const float* __restrict__ upd,       // [N,D,H]
             const float* __restrict__ dgn,       // [N,D,H]
             const float* __restrict__ bias_w,    // [N,D]
             const float* __restrict__ debias_w,  // [N,D]
             float* __restrict__ out,
             int n_tokens)
{
    extern __shared__ float xs[];                 // [TB][DD]  (64 KB)
    __shared__ float gates[TB][NCON];
    __shared__ float nx2s[TB];
    __shared__ float muWs[NCON][SR];
    __shared__ float mun2s[NCON];
    __shared__ float hsm[TB][2][HR];

    const int tid  = threadIdx.x;
    const int warp = tid >> 5;
    const int lane = tid & 31;
    const long tok0 = (long)blockIdx.x * TB;

    // ---- phase 0: stage x tile (coalesced float4) ----
    {
        const float4* xg = reinterpret_cast<const float4*>(x + tok0 * DD);
        float4* xs4 = reinterpret_cast<float4*>(xs);
        #pragma unroll
        for (int i = tid; i < TB * DD / 4; i += NT)
            xs4[i] = xg[i];
    }
    __syncthreads();

    // ---- phase 0b: warps 0-7: ||x||^2 per token; warps 8-15: muW, ||mu||^2 ----
    if (warp < TB) {
        const int t = warp;
        float a = 0.f;
        #pragma unroll 4
        for (int k = 0; k < DD / 32; k++) {
            const float v = xs[t * DD + lane + 32 * k];
            a = fmaf(v, v, a);
        }
        a = warp_sum(a);
        if (lane == 0) nx2s[t] = a;
    } else {
        const int n = warp - TB;
        const float* Wn  = Wsel + (long)n * DD * SR;
        const float* mun = mu + n * DD;
        float acc[SR];
        float m2 = 0.f;
        #pragma unroll
        for (int s = 0; s < SR; s++) acc[s] = 0.f;
        for (int k = 0; k < DD / 32; k++) {
            const int d = lane + 32 * k;
            const float  m  = __ldg(mun + d);
            const float4 wa = *reinterpret_cast<const float4*>(Wn + d * SR);
            const float4 wb = *reinterpret_cast<const float4*>(Wn + d * SR + 4);
            m2 = fmaf(m, m, m2);
            acc[0] = fmaf(wa.x, m, acc[0]);
            acc[1] = fmaf(wa.y, m, acc[1]);
            acc[2] = fmaf(wa.z, m, acc[2]);
            acc[3] = fmaf(wa.w, m, acc[3]);
            acc[4] = fmaf(wb.x, m, acc[4]);
            acc[5] = fmaf(wb.y, m, acc[5]);
            acc[6] = fmaf(wb.z, m, acc[6]);
            acc[7] = fmaf(wb.w, m, acc[7]);
        }
        #pragma unroll
        for (int s = 0; s < SR; s++) {
            const float v = warp_sum(acc[s]);
            if (lane == 0) muWs[n][s] = v;
        }
        m2 = warp_sum(m2);
        if (lane == 0) mun2s[n] = m2;
    }
    __syncthreads();

    // ---- phase 1: warp -> (concept, 4-token group) ----
    {
        const int n  = warp >> 1;
        const int tg = (warp & 1) * 4;

        float acc[4][SR];
        float xm[4];
        #pragma unroll
        for (int t = 0; t < 4; t++) {
            xm[t] = 0.f;
            #pragma unroll
            for (int s = 0; s < SR; s++) acc[t][s] = 0.f;
        }

        const float* Wn  = Wsel + (long)n * DD * SR;
        const float* mun = mu + n * DD;

        for (int k = 0; k < DD / 32; k++) {
            const int d = lane + 32 * k;
            const float  m  = __ldg(mun + d);
            const float4 wa = *reinterpret_cast<const float4*>(Wn + d * SR);
            const float4 wb = *reinterpret_cast<const float4*>(Wn + d * SR + 4);
            #pragma unroll
            for (int t = 0; t < 4; t++) {
                const float xv = xs[(tg + t) * DD + d];
                xm[t]     = fmaf(m,    xv, xm[t]);
                acc[t][0] = fmaf(wa.x, xv, acc[t][0]);
                acc[t][1] = fmaf(wa.y, xv, acc[t][1]);
                acc[t][2] = fmaf(wa.z, xv, acc[t][2]);
                acc[t][3] = fmaf(wa.w, xv, acc[t][3]);
                acc[t][4] = fmaf(wb.x, xv, acc[t][4]);
                acc[t][5] = fmaf(wb.y, xv, acc[t][5]);
                acc[t][6] = fmaf(wb.z, xv, acc[t][6]);
                acc[t][7] = fmaf(wb.w, xv, acc[t][7]);
            }
        }

        const float cn = __ldg(center + n);
        const float sn = __ldg(slope + n);
        #pragma unroll
        for (int t = 0; t < 4; t++) {
            const float xmr = warp_sum(xm[t]);
            float sc = 0.f;
            #pragma unroll
            for (int s = 0; s < SR; s++) {
                const float v = warp_sum(acc[t][s]) - muWs[n][s];
                sc = fmaf(v, v, sc);
            }
            if (lane == 0) {
                const float denom = nx2s[tg + t] - 2.f * xmr + mun2s[n];
                const float score = sc / denom;
                const float z = sn * (score - cn);
                gates[tg + t][n] = 1.f / (1.f + expf(-z));
            }
        }
    }
    __syncthreads();

    // ---- phase 2: warp -> (token, D-half) ----
    {
        const int t    = warp >> 1;
        const int half = warp & 1;
        const int dbase = half * (DD / 2);

        float best = gates[t][0];
        int bidx = 0;
        #pragma unroll
        for (int n = 1; n < NCON; n++) {
            const float g = gates[t][n];
            if (g > best) { best = g; bidx = n; }
        }
        const float sscale = best;
        const int   n = bidx;

        const float* updn = upd + (long)n * DD * HR;
        const float* dgnn = dgn + (long)n * DD * HR;
        const float* dbn  = debias_w + n * DD;
        const float* bn   = bias_w + n * DD;

        float h[HR];
        #pragma unroll
        for (int j = 0; j < HR; j++) h[j] = 0.f;

        for (int k = 0; k < DD / 64; k++) {
            const int d = dbase + lane + 32 * k;
            const float xd = xs[t * DD + d] - __ldg(dbn + d);
            const float4 ua = *reinterpret_cast<const float4*>(updn + d * HR);
            const float4 ub = *reinterpret_cast<const float4*>(updn + d * HR + 4);
            h[0] = fmaf(ua.x, xd, h[0]);
            h[1] = fmaf(ua.y, xd, h[1]);
            h[2] = fmaf(ua.z, xd, h[2]);
            h[3] = fmaf(ua.w, xd, h[3]);
            h[4] = fmaf(ub.x, xd, h[4]);
            h[5] = fmaf(ub.y, xd, h[5]);
            h[6] = fmaf(ub.z, xd, h[6]);
            h[7] = fmaf(ub.w, xd, h[7]);
        }
        #pragma unroll
        for (int j = 0; j < HR; j++) h[j] = warp_sum(h[j]);
        if (lane == 0) {
            #pragma unroll
            for (int j = 0; j < HR; j++) hsm[t][half][j] = h[j];
        }
        __syncthreads();

        float hf[HR];
        #pragma unroll
        for (int j = 0; j < HR; j++) hf[j] = hsm[t][0][j] + hsm[t][1][j];

        float* outp = out + (tok0 + t) * DD;
        const float oms = 1.f - sscale;
        for (int k = 0; k < DD / 64; k++) {
            const int d = dbase + lane + 32 * k;
            const float4 da = *reinterpret_cast<const float4*>(dgnn + d * HR);
            const float4 db = *reinterpret_cast<const float4*>(dgnn + d * HR + 4);
            float dv = da.x * hf[0];
            dv = fmaf(da.y, hf[1], dv);
            dv = fmaf(da.z, hf[2], dv);
            dv = fmaf(da.w, hf[3], dv);
            dv = fmaf(db.x, hf[4], dv);
            dv = fmaf(db.y, hf[5], dv);
            dv = fmaf(db.z, hf[6], dv);
            dv = fmaf(db.w, hf[7], dv);
            outp[d] = oms * xs[t * DD + d] + sscale * (__ldg(bn + d) + dv);
        }
    }
}

extern "C" void kernel_launch(void* const* d_in, const int* in_sizes, int n_in,
                              void* d_out, int out_size) {
    const float* x      = (const float*)d_in[0];
    const float* Wsel   = (const float*)d_in[1];
    const float* mu     = (const float*)d_in[2];
    const float* center = (const float*)d_in[3];
    const float* slope  = (const float*)d_in[4];
    const float* upd    = (const float*)d_in[5];
    const float* dgn    = (const float*)d_in[6];
    const float* bias_w = (const float*)d_in[7];
    const float* debias = (const float*)d_in[8];
    float* out = (float*)d_out;

    const int tokens = in_sizes[0] / DD;                    // B*T = 4096
    const int grid   = tokens / TB;                         // 512 blocks
    const size_t smem = (size_t)TB * DD * sizeof(float);    // 64 KB

    cudaFuncSetAttribute(gloce_kernel,
                         cudaFuncAttributeMaxDynamicSharedMemorySize,
                         (int)smem);
    gloce_kernel<<<grid, NT, smem>>>(
        x, Wsel, mu, center, slope, upd, dgn, bias_w, debias, out, tokens);
}

// round 4
// speedup vs baseline: 1.0372x; 1.0372x over previous
#include <cuda_runtime.h>

// GLoCELayerOutProp: B=4, T=1024, D=2048, N=8 concepts, S=8, H=8, ETA=1.
//
// R1 structure (warp=concept x 8 tokens, 64KB x-tile, minimal W traffic)
// + packed f32x2 math (fma.rn.f32x2 = FFMA2, 2 fp32 FMAs per instruction,
//   bit-exact fp32). Phase 1 packs token pairs; phase 2 packs d-pairs.

#define DD      2048
#define NCON    8
#define SR      8
#define HR      8
#define TB      8
#define NTHREADS 256

typedef unsigned long long u64;

#define FMA2(d, a, b, c) \
    asm("fma.rn.f32x2 %0, %1, %2, %3;" : "=l"(d) : "l"(a), "l"(b), "l"(c))
#define ADD2(d, a, b) \
    asm("add.rn.f32x2 %0, %1, %2;" : "=l"(d) : "l"(a), "l"(b))
#define MUL2(d, a, b) \
    asm("mul.rn.f32x2 %0, %1, %2;" : "=l"(d) : "l"(a), "l"(b))
#define PACK2(out, lo, hi) \
    asm("mov.b64 %0, {%1, %2};" : "=l"(out) : "r"(__float_as_uint(lo)), "r"(__float_as_uint(hi)))
#define UNPACK2(lo, hi, in) \
    do { unsigned _l, _h; \
         asm("mov.b64 {%0, %1}, %2;" : "=r"(_l), "=r"(_h) : "l"(in)); \
         lo = __uint_as_float(_l); hi = __uint_as_float(_h); } while (0)

__device__ __forceinline__ float warp_sum(float v) {
    #pragma unroll
    for (int o = 16; o > 0; o >>= 1) v += __shfl_xor_sync(0xffffffffu, v, o);
    return v;
}

__global__ void __launch_bounds__(NTHREADS, 2)
gloce_kernel(const float* __restrict__ x,
             const float* __restrict__ Wsel,      // [N,D,S]
             const float* __restrict__ mu,        // [N,D]
             const float* __restrict__ center,    // [N]
             const float* __restrict__ slope,     // [N]
             const float* __restrict__ upd,       // [N,D,H]
             const float* __restrict__ dgn,       // [N,D,H]
             const float* __restrict__ bias_w,    // [N,D]
             const float* __restrict__ debias_w,  // [N,D]
             float* __restrict__ out,
             int n_tokens)
{
    extern __shared__ float xs[];                 // [TB][DD]  (64 KB)
    __shared__ float gates[TB][NCON];

    const int tid  = threadIdx.x;
    const int warp = tid >> 5;
    const int lane = tid & 31;
    const long tok0 = (long)blockIdx.x * TB;

    // ---- stage x tile into smem (coalesced float4) ----
    {
        const float4* xg = reinterpret_cast<const float4*>(x + tok0 * DD);
        float4* xs4 = reinterpret_cast<float4*>(xs);
        #pragma unroll 4
        for (int i = tid; i < TB * DD / 4; i += NTHREADS)
            xs4[i] = xg[i];
    }
    __syncthreads();

    // ---- phase 1: warp = concept, all 8 tokens, token-pair packed f32x2 ----
    {
        const int n = warp;
        u64 acc2[4][SR];          // (token 2p, token 2p+1) packed
        u64 nrm2[4];
        #pragma unroll
        for (int p = 0; p < 4; p++) {
            nrm2[p] = 0ull;
            #pragma unroll
            for (int s = 0; s < SR; s++) acc2[p][s] = 0ull;
        }

        const float* Wn  = Wsel + (long)n * DD * SR;
        const float* mun = mu + n * DD;

        #pragma unroll 2
        for (int k = 0; k < DD / 32; k++) {
            const int d = lane + 32 * k;
            const float m = __ldg(mun + d);
            const float nm = -m;
            u64 nm2; PACK2(nm2, nm, nm);
            const float4 wa = *reinterpret_cast<const float4*>(Wn + d * SR);
            const float4 wb = *reinterpret_cast<const float4*>(Wn + d * SR + 4);
            u64 w2[SR];
            PACK2(w2[0], wa.x, wa.x);  PACK2(w2[1], wa.y, wa.y);
            PACK2(w2[2], wa.z, wa.z);  PACK2(w2[3], wa.w, wa.w);
            PACK2(w2[4], wb.x, wb.x);  PACK2(w2[5], wb.y, wb.y);
            PACK2(w2[6], wb.z, wb.z);  PACK2(w2[7], wb.w, wb.w);
            #pragma unroll
            for (int p = 0; p < 4; p++) {
                const float x0 = xs[(2 * p) * DD + d];
                const float x1 = xs[(2 * p + 1) * DD + d];
                u64 xv2; PACK2(xv2, x0, x1);
                u64 diff2; ADD2(diff2, xv2, nm2);
                FMA2(nrm2[p], diff2, diff2, nrm2[p]);
                #pragma unroll
                for (int s = 0; s < SR; s++)
                    FMA2(acc2[p][s], w2[s], diff2, acc2[p][s]);
            }
        }

        const float cn = __ldg(center + n);
        const float sn = __ldg(slope + n);
        #pragma unroll
        for (int p = 0; p < 4; p++) {
            float n0, n1; UNPACK2(n0, n1, nrm2[p]);
            const float nr0 = warp_sum(n0);
            const float nr1 = warp_sum(n1);
            float sc0 = 0.f, sc1 = 0.f;
            #pragma unroll
            for (int s = 0; s < SR; s++) {
                float a0, a1; UNPACK2(a0, a1, acc2[p][s]);
                const float v0 = warp_sum(a0);
                const float v1 = warp_sum(a1);
                sc0 = fmaf(v0, v0, sc0);
                sc1 = fmaf(v1, v1, sc1);
            }
            if (lane == 0) {
                const float z0 = sn * (sc0 / nr0 - cn);
                const float z1 = sn * (sc1 / nr1 - cn);
                gates[2 * p][n]     = 1.f / (1.f + expf(-z0));
                gates[2 * p + 1][n] = 1.f / (1.f + expf(-z1));
            }
        }
    }
    __syncthreads();

    // ---- phase 2: warp = token, d-pair packed f32x2 ----
    {
        const int t = warp;
        float best = gates[t][0];
        int bidx = 0;
        #pragma unroll
        for (int n = 1; n < NCON; n++) {
            const float g = gates[t][n];
            if (g > best) { best = g; bidx = n; }
        }
        const float sscale = best;
        const int   n = bidx;

        const float* updn = upd + (long)n * DD * HR;
        const float* dgnn = dgn + (long)n * DD * HR;
        const float* dbn  = debias_w + n * DD;
        const float* bn   = bias_w + n * DD;
        const float2* xs2 = reinterpret_cast<const float2*>(xs + t * DD);

        u64 negone2; { const float no = -1.f; PACK2(negone2, no, no); }

        u64 h2[HR];
        #pragma unroll
        for (int j = 0; j < HR; j++) h2[j] = 0ull;

        #pragma unroll 2
        for (int k = 0; k < DD / 64; k++) {
            const int d = 2 * lane + 64 * k;          // even
            const float2 xv = xs2[d >> 1];
            u64 xv2; PACK2(xv2, xv.x, xv.y);
            const float2 db = *reinterpret_cast<const float2*>(dbn + d);
            u64 db2; PACK2(db2, db.x, db.y);
            u64 xd2; FMA2(xd2, db2, negone2, xv2);    // x - debias
            const float4 u0a = *reinterpret_cast<const float4*>(updn + d * HR);
            const float4 u0b = *reinterpret_cast<const float4*>(updn + d * HR + 4);
            const float4 u1a = *reinterpret_cast<const float4*>(updn + d * HR + 8);
            const float4 u1b = *reinterpret_cast<const float4*>(updn + d * HR + 12);
            u64 u2;
            PACK2(u2, u0a.x, u1a.x); FMA2(h2[0], u2, xd2, h2[0]);
            PACK2(u2, u0a.y, u1a.y); FMA2(h2[1], u2, xd2, h2[1]);
            PACK2(u2, u0a.z, u1a.z); FMA2(h2[2], u2, xd2, h2[2]);
            PACK2(u2, u0a.w, u1a.w); FMA2(h2[3], u2, xd2, h2[3]);
            PACK2(u2, u0b.x, u1b.x); FMA2(h2[4], u2, xd2, h2[4]);
            PACK2(u2, u0b.y, u1b.y); FMA2(h2[5], u2, xd2, h2[5]);
            PACK2(u2, u0b.z, u1b.z); FMA2(h2[6], u2, xd2, h2[6]);
            PACK2(u2, u0b.w, u1b.w); FMA2(h2[7], u2, xd2, h2[7]);
        }

        float hf[HR];
        #pragma unroll
        for (int j = 0; j < HR; j++) {
            float l, h; UNPACK2(l, h, h2[j]);
            hf[j] = warp_sum(l + h);
        }

        u64 hf2[HR];
        #pragma unroll
        for (int j = 0; j < HR; j++) PACK2(hf2[j], hf[j], hf[j]);

        const float oms = 1.f - sscale;
        u64 s2, oms2;
        PACK2(s2, sscale, sscale);
        PACK2(oms2, oms, oms);

        float* outp = out + (tok0 + t) * DD;
        #pragma unroll 2
        for (int k = 0; k < DD / 64; k++) {
            const int d = 2 * lane + 64 * k;
            const float4 g0a = *reinterpret_cast<const float4*>(dgnn + d * HR);
            const float4 g0b = *reinterpret_cast<const float4*>(dgnn + d * HR + 4);
            const float4 g1a = *reinterpret_cast<const float4*>(dgnn + d * HR + 8);
            const float4 g1b = *reinterpret_cast<const float4*>(dgnn + d * HR + 12);
            u64 g2, dv2;
            PACK2(g2, g0a.x, g1a.x); MUL2(dv2, g2, hf2[0]);
            PACK2(g2, g0a.y, g1a.y); FMA2(dv2, g2, hf2[1], dv2);
            PACK2(g2, g0a.z, g1a.z); FMA2(dv2, g2, hf2[2], dv2);
            PACK2(g2, g0a.w, g1a.w); FMA2(dv2, g2, hf2[3], dv2);
            PACK2(g2, g0b.x, g1b.x); FMA2(dv2, g2, hf2[4], dv2);
            PACK2(g2, g0b.y, g1b.y); FMA2(dv2, g2, hf2[5], dv2);
            PACK2(g2, g0b.z, g1b.z); FMA2(dv2, g2, hf2[6], dv2);
            PACK2(g2, g0b.w, g1b.w); FMA2(dv2, g2, hf2[7], dv2);

            const float2 bv = *reinterpret_cast<const float2*>(bn + d);
            u64 b2; PACK2(b2, bv.x, bv.y);
            const float2 xv = xs2[d >> 1];
            u64 xv2; PACK2(xv2, xv.x, xv.y);

            u64 tmp2, r2;
            ADD2(tmp2, b2, dv2);          // bias + degen
            MUL2(r2, s2, tmp2);           // s * (...)
            FMA2(r2, oms2, xv2, r2);      // + (1-s) * x

            float r0, r1; UNPACK2(r0, r1, r2);
            *reinterpret_cast<float2*>(outp + d) = make_float2(r0, r1);
        }
    }
}

extern "C" void kernel_launch(void* const* d_in, const int* in_sizes, int n_in,
                              void* d_out, int out_size) {
    const float* x      = (const float*)d_in[0];
    const float* Wsel   = (const float*)d_in[1];
    const float* mu     = (const float*)d_in[2];
    const float* center = (const float*)d_in[3];
    const float* slope  = (const float*)d_in[4];
    const float* upd    = (const float*)d_in[5];
    const float* dgn    = (const float*)d_in[6];
    const float* bias_w = (const float*)d_in[7];
    const float* debias = (const float*)d_in[8];
    float* out = (float*)d_out;

    const int tokens = in_sizes[0] / DD;                    // B*T = 4096
    const int grid   = tokens / TB;                         // 512 blocks
    const size_t smem = (size_t)TB * DD * sizeof(float);    // 64 KB

    cudaFuncSetAttribute(gloce_kernel,
                         cudaFuncAttributeMaxDynamicSharedMemorySize,
                         (int)smem);
    gloce_kernel<<<grid, NTHREADS, smem>>>(
        x, Wsel, mu, center, slope, upd, dgn, bias_w, debias, out, tokens);
}

// round 5
// speedup vs baseline: 1.5674x; 1.5111x over previous
#include <cuda_runtime.h>

// GLoCELayerOutProp: B=4, T=1024, D=2048, N=8 concepts, S=8, H=8, ETA=1.
//
// R1 base (warp=concept x 8 tokens in phase 1, 64KB x-tile, minimal W traffic):
//  + phase-1 software prefetch (double-buffered W/mu; first loads issued
//    before the staging barrier) to hide ~240cyc L2-hit latency.
//  + phase-2 restructured: warp = 256-dim D-slice over ALL 8 tokens, looping
//    over the (few) concepts actually selected. upd/dgn rows are loaded once
//    per 4-token group instead of once per token (~4x fewer LDG in the common
//    uniform-concept case), and all warps stay busy for any concept mix.
//    Partial h reduced via shfl + smem across warps.

#define DD      2048
#define NCON    8
#define SR      8
#define HR      8
#define TB      8
#define NTHREADS 256

__device__ __forceinline__ float warp_sum(float v) {
    #pragma unroll
    for (int o = 16; o > 0; o >>= 1) v += __shfl_xor_sync(0xffffffffu, v, o);
    return v;
}

__global__ void __launch_bounds__(NTHREADS, 2)
gloce_kernel(const float* __restrict__ x,
             const float* __restrict__ Wsel,      // [N,D,S]
             const float* __restrict__ mu,        // [N,D]
             const float* __restrict__ center,    // [N]
             const float* __restrict__ slope,     // [N]
             const float* __restrict__ upd,       // [N,D,H]
             const float* __restrict__ dgn,       // [N,D,H]
             const float* __restrict__ bias_w,    // [N,D]
             const float* __restrict__ debias_w,  // [N,D]
             float* __restrict__ out,
             int n_tokens)
{
    extern __shared__ float xs[];                 // [TB][DD]  (64 KB)
    __shared__ float gates[TB][NCON];
    __shared__ float hpart[TB][NCON][HR];         // [token][warp][j]  2 KB
    __shared__ float hf_s[TB][HR];

    const int tid  = threadIdx.x;
    const int warp = tid >> 5;
    const int lane = tid & 31;
    const long tok0 = (long)blockIdx.x * TB;

    // ---- stage x tile into smem (coalesced float4) ----
    {
        const float4* xg = reinterpret_cast<const float4*>(x + tok0 * DD);
        float4* xs4 = reinterpret_cast<float4*>(xs);
        #pragma unroll 4
        for (int i = tid; i < TB * DD / 4; i += NTHREADS)
            xs4[i] = xg[i];
    }

    // ---- phase-1 prefetch (independent of xs; overlaps the barrier) ----
    const int n1 = warp;                          // concept for phase 1
    const float* Wn  = Wsel + (long)n1 * DD * SR;
    const float* mun = mu + n1 * DD;
    float  m_nb  = __ldg(mun + lane);
    float4 wa_nb = __ldg(reinterpret_cast<const float4*>(Wn + lane * SR));
    float4 wb_nb = __ldg(reinterpret_cast<const float4*>(Wn + lane * SR + 4));

    __syncthreads();

    // ---- phase 1: warp = concept, all 8 tokens ----
    {
        float acc[TB][SR];
        float nrm[TB];
        #pragma unroll
        for (int t = 0; t < TB; t++) {
            nrm[t] = 0.f;
            #pragma unroll
            for (int s = 0; s < SR; s++) acc[t][s] = 0.f;
        }

        #pragma unroll 1
        for (int k = 0; k < DD / 32; k++) {
            const float  m  = m_nb;
            const float4 wa = wa_nb;
            const float4 wb = wb_nb;
            if (k < DD / 32 - 1) {
                const int dn = lane + 32 * (k + 1);
                m_nb  = __ldg(mun + dn);
                wa_nb = __ldg(reinterpret_cast<const float4*>(Wn + dn * SR));
                wb_nb = __ldg(reinterpret_cast<const float4*>(Wn + dn * SR + 4));
            }
            const int d = lane + 32 * k;
            #pragma unroll
            for (int t = 0; t < TB; t++) {
                const float diff = xs[t * DD + d] - m;
                nrm[t]    = fmaf(diff, diff, nrm[t]);
                acc[t][0] = fmaf(wa.x, diff, acc[t][0]);
                acc[t][1] = fmaf(wa.y, diff, acc[t][1]);
                acc[t][2] = fmaf(wa.z, diff, acc[t][2]);
                acc[t][3] = fmaf(wa.w, diff, acc[t][3]);
                acc[t][4] = fmaf(wb.x, diff, acc[t][4]);
                acc[t][5] = fmaf(wb.y, diff, acc[t][5]);
                acc[t][6] = fmaf(wb.z, diff, acc[t][6]);
                acc[t][7] = fmaf(wb.w, diff, acc[t][7]);
            }
        }

        const float cn = __ldg(center + n1);
        const float sn = __ldg(slope + n1);
        #pragma unroll
        for (int t = 0; t < TB; t++) {
            const float nr = warp_sum(nrm[t]);
            float sc = 0.f;
            #pragma unroll
            for (int s = 0; s < SR; s++) {
                const float v = warp_sum(acc[t][s]);
                sc = fmaf(v, v, sc);
            }
            if (lane == 0) {
                const float score = sc / nr;
                const float z = sn * (score - cn);
                gates[t][n1] = 1.f / (1.f + __expf(-z));
            }
        }
    }
    __syncthreads();

    // ---- phase 2: warp = D-slice [warp*256, warp*256+256), all tokens ----
    int   selc[TB];
    float ssc[TB];
    unsigned present = 0u;
    #pragma unroll
    for (int t = 0; t < TB; t++) {
        float best = gates[t][0];
        int bi = 0;
        #pragma unroll
        for (int n = 1; n < NCON; n++) {
            const float g = gates[t][n];
            if (g > best) { best = g; bi = n; }
        }
        selc[t] = bi;
        ssc[t]  = best;
        present |= 1u << bi;
    }

    const int d0 = warp * (DD / NCON);            // 256-dim slice

    // --- h accumulation in two 4-token groups ---
    #pragma unroll 1
    for (int g = 0; g < 2; g++) {
        float h[4][HR];
        #pragma unroll
        for (int tt = 0; tt < 4; tt++)
            #pragma unroll
            for (int j = 0; j < HR; j++) h[tt][j] = 0.f;

        #pragma unroll 1
        for (int c = 0; c < NCON; c++) {
            if (!((present >> c) & 1u)) continue;
            bool any = false;
            #pragma unroll
            for (int tt = 0; tt < 4; tt++) any |= (selc[g * 4 + tt] == c);
            if (!any) continue;

            const float* updc = upd + (long)c * DD * HR;
            const float* dbc  = debias_w + c * DD;
            #pragma unroll 2
            for (int i = 0; i < 8; i++) {
                const int d = d0 + lane + 32 * i;
                const float db = __ldg(dbc + d);
                const float4 ua = __ldg(reinterpret_cast<const float4*>(updc + d * HR));
                const float4 ub = __ldg(reinterpret_cast<const float4*>(updc + d * HR + 4));
                #pragma unroll
                for (int tt = 0; tt < 4; tt++) {
                    const int t = g * 4 + tt;
                    if (selc[t] == c) {
                        const float xd = xs[t * DD + d] - db;
                        h[tt][0] = fmaf(ua.x, xd, h[tt][0]);
                        h[tt][1] = fmaf(ua.y, xd, h[tt][1]);
                        h[tt][2] = fmaf(ua.z, xd, h[tt][2]);
                        h[tt][3] = fmaf(ua.w, xd, h[tt][3]);
                        h[tt][4] = fmaf(ub.x, xd, h[tt][4]);
                        h[tt][5] = fmaf(ub.y, xd, h[tt][5]);
                        h[tt][6] = fmaf(ub.z, xd, h[tt][6]);
                        h[tt][7] = fmaf(ub.w, xd, h[tt][7]);
                    }
                }
            }
        }
        #pragma unroll
        for (int tt = 0; tt < 4; tt++) {
            #pragma unroll
            for (int j = 0; j < HR; j++) {
                const float v = warp_sum(h[tt][j]);
                if (lane == 0) hpart[g * 4 + tt][warp][j] = v;
            }
        }
    }
    __syncthreads();

    // --- cross-warp reduction of h: 64 (t,j) pairs ---
    if (tid < TB * HR) {
        const int t = tid >> 3, j = tid & 7;
        float s = 0.f;
        #pragma unroll
        for (int w = 0; w < NCON; w++) s += hpart[t][w][j];
        hf_s[t][j] = s;
    }
    __syncthreads();

    // --- output in two 4-token groups ---
    #pragma unroll 1
    for (int g = 0; g < 2; g++) {
        float hf[4][HR];
        #pragma unroll
        for (int tt = 0; tt < 4; tt++)
            #pragma unroll
            for (int j = 0; j < HR; j++) hf[tt][j] = hf_s[g * 4 + tt][j];

        #pragma unroll 1
        for (int c = 0; c < NCON; c++) {
            if (!((present >> c) & 1u)) continue;
            bool any = false;
            #pragma unroll
            for (int tt = 0; tt < 4; tt++) any |= (selc[g * 4 + tt] == c);
            if (!any) continue;

            const float* dgnc = dgn + (long)c * DD * HR;
            const float* bnc  = bias_w + c * DD;
            #pragma unroll 2
            for (int i = 0; i < 8; i++) {
                const int d = d0 + lane + 32 * i;
                const float bv = __ldg(bnc + d);
                const float4 ga = __ldg(reinterpret_cast<const float4*>(dgnc + d * HR));
                const float4 gb = __ldg(reinterpret_cast<const float4*>(dgnc + d * HR + 4));
                #pragma unroll
                for (int tt = 0; tt < 4; tt++) {
                    const int t = g * 4 + tt;
                    if (selc[t] == c) {
                        float dv = ga.x * hf[tt][0];
                        dv = fmaf(ga.y, hf[tt][1], dv);
                        dv = fmaf(ga.z, hf[tt][2], dv);
                        dv = fmaf(ga.w, hf[tt][3], dv);
                        dv = fmaf(gb.x, hf[tt][4], dv);
                        dv = fmaf(gb.y, hf[tt][5], dv);
                        dv = fmaf(gb.z, hf[tt][6], dv);
                        dv = fmaf(gb.w, hf[tt][7], dv);
                        const float s = ssc[t];
                        out[(tok0 + t) * DD + d] =
                            (1.f - s) * xs[t * DD + d] + s * (bv + dv);
                    }
                }
            }
        }
    }
}

extern "C" void kernel_launch(void* const* d_in, const int* in_sizes, int n_in,
                              void* d_out, int out_size) {
    const float* x      = (const float*)d_in[0];
    const float* Wsel   = (const float*)d_in[1];
    const float* mu     = (const float*)d_in[2];
    const float* center = (const float*)d_in[3];
    const float* slope  = (const float*)d_in[4];
    const float* upd    = (const float*)d_in[5];
    const float* dgn    = (const float*)d_in[6];
    const float* bias_w = (const float*)d_in[7];
    const float* debias = (const float*)d_in[8];
    float* out = (float*)d_out;

    const int tokens = in_sizes[0] / DD;                    // B*T = 4096
    const int grid   = tokens / TB;                         // 512 blocks
    const size_t smem = (size_t)TB * DD * sizeof(float);    // 64 KB

    cudaFuncSetAttribute(gloce_kernel,
                         cudaFuncAttributeMaxDynamicSharedMemorySize,
                         (int)smem);
    gloce_kernel<<<grid, NTHREADS, smem>>>(
        x, Wsel, mu, center, slope, upd, dgn, bias_w, debias, out, tokens);
}